// round 9
// baseline (speedup 1.0000x reference)
#include <cuda_runtime.h>

#define GRIDW 32
#define BATCH 64
#define NPTS  16384
#define GCNT  (GRIDW*GRIDW*GRIDW)       // 32768
#define TPB   512
#define HALVES 8                         // blocks per batch
#define PTS_PER_BLOCK (NPTS/HALVES)      // 2048
#define PPT_ITERS (PTS_PER_BLOCK/TPB)    // 4 points per thread
#define MAIN_GRID (BATCH*HALVES)         // 512
#define SPLIT_FLAT 18432                 // cells with ix<18 live in smem (72 KB)

__device__ double   g_acc = 0.0;
__device__ unsigned g_cnt = 0u;
__device__ unsigned g_packed[BATCH * GCNT];   // 8 MB quantized global table

struct SmemLayout {
    unsigned tab[SPLIT_FLAT];  // 73728 B: quantized cells, flat < 18432
    float4   mat[6][3];        // affine rows: (a0,a1,a2,t)
    float    red[TPB/32];
};
#define SMEM_BYTES ((int)sizeof(SmemLayout))

__device__ __forceinline__ float sqrt_approx(float x) {
    float r; asm("sqrt.approx.f32 %0, %1;" : "=f"(r) : "f"(x)); return r;
}
__device__ __forceinline__ int cell_clamp(float s) {
    return __float2int_rd(fminf(fmaxf(s, 0.f), 31.f));
}

// ---------------- prelude: quantize closest -> u32 table in gmem ----------------
// x: 10 bits (step 1/32), y/z: 11 bits (step 1/64)
__global__ __launch_bounds__(256)
void sdl_repack_kernel(const float* __restrict__ closest) {
    int i = blockIdx.x * 256 + threadIdx.x;       // over BATCH*GCNT
    const float* s = closest + (size_t)i * 3;
    unsigned ux = (unsigned)min(1023, max(0, __float2int_rn(s[0] * 32.f)));
    unsigned uy = (unsigned)min(2047, max(0, __float2int_rn(s[1] * 64.f)));
    unsigned uz = (unsigned)min(2047, max(0, __float2int_rn(s[2] * 64.f)));
    g_packed[i] = ux | (uy << 10) | (uz << 21);
}

// ---------------- main ----------------
__global__ __launch_bounds__(TPB, 3)
void sdl_main_kernel(const float* __restrict__ prm,
                     const float* __restrict__ points,
                     float* __restrict__ out) {
    extern __shared__ unsigned char smem_raw[];
    SmemLayout* sm = reinterpret_cast<SmemLayout*>(smem_raw);

    const int b    = blockIdx.x >> 3;               // / HALVES
    const int part = blockIdx.x & (HALVES - 1);
    const int tid  = threadIdx.x;
    const float* op = prm + b * 24;

    // ---- build 6 affine transforms (one thread each) ----
    if (tid < 6) {
        float4 r0, r1, r2;
        if (tid < 3) {                       // reflection
            const float* pp = op + tid * 4;
            float nx = pp[0], ny = pp[1], nz = pp[2], d = pp[3];
            float inv = __frcp_rn(nx*nx + ny*ny + nz*nz);
            float kx = 2.f*inv*nx, ky = 2.f*inv*ny, kz = 2.f*inv*nz;
            r0 = make_float4(1.f - kx*nx,     -kx*ny,     -kx*nz, -d*kx);
            r1 = make_float4(    -ky*nx, 1.f - ky*ny,     -ky*nz, -d*ky);
            r2 = make_float4(    -kz*nx,     -kz*ny, 1.f - kz*nz, -d*kz);
        } else {                             // rotation scaled by 1/|q|
            const float* qq = op + tid * 4;
            float w = qq[0], x = qq[1], y = qq[2], z = qq[3];
            float iv = rsqrtf(w*w + x*x + y*y + z*z);
            r0 = make_float4((w*w + x*x - y*y - z*z)*iv, 2.f*(x*y - w*z)*iv,
                             2.f*(x*z + w*y)*iv, 0.f);
            r1 = make_float4(2.f*(x*y + w*z)*iv, (w*w - x*x + y*y - z*z)*iv,
                             2.f*(y*z - w*x)*iv, 0.f);
            r2 = make_float4(2.f*(x*z - w*y)*iv, 2.f*(y*z + w*x)*iv,
                             (w*w - x*x - y*y + z*z)*iv, 0.f);
        }
        sm->mat[tid][0] = r0; sm->mat[tid][1] = r1; sm->mat[tid][2] = r2;
    }

    // ---- copy smem part of this batch's table (coalesced uint4) ----
    {
        const uint4* src = reinterpret_cast<const uint4*>(g_packed + (size_t)b * GCNT);
        uint4* dst = reinterpret_cast<uint4*>(sm->tab);
        for (int i = tid; i < SPLIT_FLAT / 4; i += TPB)
            dst[i] = __ldg(&src[i]);
    }
    __syncthreads();

    const unsigned* __restrict__ gtab = g_packed + (size_t)b * GCNT;
    const float* pbase = points + ((size_t)b * NPTS + (size_t)part * PTS_PER_BLOCK) * 3;

    float acc = 0.f;

    #pragma unroll
    for (int it = 0; it < PPT_ITERS; it++) {
        const float* p = pbase + ((size_t)it * TPB + tid) * 3;
        const float px = __ldg(p + 0);
        const float py = __ldg(p + 1);
        const float pz = __ldg(p + 2);

        // two groups of 3 symmetries: small live register set
        #pragma unroll
        for (int g = 0; g < 2; g++) {
            float sx[3], sy[3], sz[3];
            #pragma unroll
            for (int j = 0; j < 3; j++) {
                const int s = g * 3 + j;
                float4 r0 = sm->mat[s][0], r1 = sm->mat[s][1], r2 = sm->mat[s][2];
                sx[j] = fmaf(r0.x, px, fmaf(r0.y, py, fmaf(r0.z, pz, r0.w)));
                sy[j] = fmaf(r1.x, px, fmaf(r1.y, py, fmaf(r1.z, pz, r1.w)));
                sz[j] = fmaf(r2.x, px, fmaf(r2.y, py, fmaf(r2.z, pz, r2.w)));
            }

            unsigned uv[3];
            #pragma unroll
            for (int j = 0; j < 3; j++) {
                int flat = (cell_clamp(sx[j]) << 10) + (cell_clamp(sy[j]) << 5)
                         + cell_clamp(sz[j]);
                uv[j] = (flat < SPLIT_FLAT) ? sm->tab[flat] : __ldg(&gtab[flat]);
            }

            #pragma unroll
            for (int j = 0; j < 3; j++) {
                unsigned u = uv[j];
                float dx = fmaf(-0.03125f,  (float)(u & 1023u),         sx[j]);
                float dy = fmaf(-0.015625f, (float)((u >> 10) & 2047u), sy[j]);
                float dz = fmaf(-0.015625f, (float)(u >> 21),           sz[j]);
                acc += sqrt_approx(dx*dx + dy*dy + dz*dz);
            }
        }
    }

    // ---- block reduce + global accumulate + fused finalize ----
    #pragma unroll
    for (int o = 16; o; o >>= 1) acc += __shfl_xor_sync(0xffffffffu, acc, o);
    if ((tid & 31) == 0) sm->red[tid >> 5] = acc;
    __syncthreads();

    if (tid == 0) {
        float v = 0.f;
        #pragma unroll
        for (int i = 0; i < TPB/32; i++) v += sm->red[i];
        atomicAdd(&g_acc, (double)v);
        __threadfence();
        unsigned t = atomicAdd(&g_cnt, 1u);
        if (t == MAIN_GRID - 1) {
            __threadfence();
            double s = g_acc;
            out[0] = (float)(s / ((double)BATCH * (double)NPTS));
            g_acc = 0.0;
            g_cnt = 0u;
            __threadfence();
        }
    }
}

extern "C" void kernel_launch(void* const* d_in, const int* in_sizes, int n_in,
                              void* d_out, int out_size) {
    const float* prm     = (const float*)d_in[0];   // (64, 6, 4)
    const float* points  = (const float*)d_in[1];   // (64, 16384, 3)
    const float* closest = (const float*)d_in[2];   // (64, 32768, 3)
    float* out = (float*)d_out;

    cudaError_t e = cudaFuncSetAttribute(sdl_main_kernel,
                                         cudaFuncAttributeMaxDynamicSharedMemorySize,
                                         SMEM_BYTES);
    (void)e;   // on failure the launch below errors loudly (invalid config)

    sdl_repack_kernel<<<(BATCH * GCNT) / 256, 256>>>(closest);
    sdl_main_kernel<<<MAIN_GRID, TPB, SMEM_BYTES>>>(prm, points, out);
}

// round 12
// speedup vs baseline: 1.2459x; 1.2459x over previous
#include <cuda_runtime.h>

#define GRIDW 32
#define BATCH 64
#define NPTS  16384
#define GCNT  (GRIDW*GRIDW*GRIDW)       // 32768
#define TPB   512
#define MAIN_GRID 296                    // = 2 * 148 SMs, balanced residency
#define SPLIT_FLAT 27648                 // cells with ix<27 live in smem (108 KB)

__device__ double   g_acc = 0.0;
__device__ unsigned g_cnt = 0u;
__device__ unsigned g_packed[BATCH * GCNT];   // 8 MB quantized global table

struct SmemLayout {
    unsigned tab[SPLIT_FLAT];  // 110592 B: quantized cells, flat < 27648
    float4   mat[6][3];        // affine rows: (a0,a1,a2,t)
    float    red[TPB/32];
};
#define SMEM_BYTES ((int)sizeof(SmemLayout))

__device__ __forceinline__ float sqrt_approx(float x) {
    float r; asm("sqrt.approx.f32 %0, %1;" : "=f"(r) : "f"(x)); return r;
}
__device__ __forceinline__ int cell_clamp(float s) {
    return __float2int_rd(fminf(fmaxf(s, 0.f), 31.f));
}

// ---------------- prelude: quantize closest -> u32 table in gmem ----------------
// x: 10 bits (step 1/32), y/z: 11 bits (step 1/64)
__global__ __launch_bounds__(256)
void sdl_repack_kernel(const float* __restrict__ closest) {
    int i = blockIdx.x * 256 + threadIdx.x;       // over BATCH*GCNT
    const float* s = closest + (size_t)i * 3;
    unsigned ux = (unsigned)min(1023, max(0, __float2int_rn(s[0] * 32.f)));
    unsigned uy = (unsigned)min(2047, max(0, __float2int_rn(s[1] * 64.f)));
    unsigned uz = (unsigned)min(2047, max(0, __float2int_rn(s[2] * 64.f)));
    g_packed[i] = ux | (uy << 10) | (uz << 21);
}

// ---------------- main ----------------
__global__ __launch_bounds__(TPB, 2)
void sdl_main_kernel(const float* __restrict__ prm,
                     const float* __restrict__ points,
                     float* __restrict__ out) {
    extern __shared__ unsigned char smem_raw[];
    SmemLayout* sm = reinterpret_cast<SmemLayout*>(smem_raw);

    // ---- balanced block -> (batch, point range) mapping ----
    // batches 0..39: 5 blocks each (bids 0..199); batches 40..63: 4 blocks (200..295)
    const int bid = blockIdx.x;
    int b, part, cnt;
    if (bid < 200) { b = bid / 5;            part = bid % 5;          cnt = 5; }
    else           { b = 40 + (bid - 200)/4; part = (bid - 200) & 3;  cnt = 4; }
    const int pstart = (part * NPTS) / cnt;
    const int pend   = ((part + 1) * NPTS) / cnt;

    const int tid  = threadIdx.x;
    const float* op = prm + b * 24;

    // ---- build 6 affine transforms (one thread each) ----
    if (tid < 6) {
        float4 r0, r1, r2;
        if (tid < 3) {                       // reflection
            const float* pp = op + tid * 4;
            float nx = pp[0], ny = pp[1], nz = pp[2], d = pp[3];
            float inv = __frcp_rn(nx*nx + ny*ny + nz*nz);
            float kx = 2.f*inv*nx, ky = 2.f*inv*ny, kz = 2.f*inv*nz;
            r0 = make_float4(1.f - kx*nx,     -kx*ny,     -kx*nz, -d*kx);
            r1 = make_float4(    -ky*nx, 1.f - ky*ny,     -ky*nz, -d*ky);
            r2 = make_float4(    -kz*nx,     -kz*ny, 1.f - kz*nz, -d*kz);
        } else {                             // rotation scaled by 1/|q|
            const float* qq = op + tid * 4;
            float w = qq[0], x = qq[1], y = qq[2], z = qq[3];
            float iv = rsqrtf(w*w + x*x + y*y + z*z);
            r0 = make_float4((w*w + x*x - y*y - z*z)*iv, 2.f*(x*y - w*z)*iv,
                             2.f*(x*z + w*y)*iv, 0.f);
            r1 = make_float4(2.f*(x*y + w*z)*iv, (w*w - x*x + y*y - z*z)*iv,
                             2.f*(y*z - w*x)*iv, 0.f);
            r2 = make_float4(2.f*(x*z - w*y)*iv, 2.f*(y*z + w*x)*iv,
                             (w*w - x*x - y*y + z*z)*iv, 0.f);
        }
        sm->mat[tid][0] = r0; sm->mat[tid][1] = r1; sm->mat[tid][2] = r2;
    }

    // ---- copy smem part of this batch's table (coalesced uint4) ----
    {
        const uint4* src = reinterpret_cast<const uint4*>(g_packed + (size_t)b * GCNT);
        uint4* dst = reinterpret_cast<uint4*>(sm->tab);
        for (int i = tid; i < SPLIT_FLAT / 4; i += TPB)
            dst[i] = __ldg(&src[i]);
    }
    __syncthreads();

    const unsigned* __restrict__ gtab = g_packed + (size_t)b * GCNT;
    const float* pbase = points + (size_t)b * NPTS * 3;

    float acc = 0.f;

    for (int i = pstart + tid; i < pend; i += TPB) {
        const float* p = pbase + (size_t)i * 3;
        const float px = __ldg(p + 0);
        const float py = __ldg(p + 1);
        const float pz = __ldg(p + 2);

        float sx[6], sy[6], sz[6];
        #pragma unroll
        for (int s = 0; s < 6; s++) {
            float4 r0 = sm->mat[s][0], r1 = sm->mat[s][1], r2 = sm->mat[s][2];
            sx[s] = fmaf(r0.x, px, fmaf(r0.y, py, fmaf(r0.z, pz, r0.w)));
            sy[s] = fmaf(r1.x, px, fmaf(r1.y, py, fmaf(r1.z, pz, r1.w)));
            sz[s] = fmaf(r2.x, px, fmaf(r2.y, py, fmaf(r2.z, pz, r2.w)));
        }

        unsigned uv[6];
        #pragma unroll
        for (int s = 0; s < 6; s++) {
            int flat = (cell_clamp(sx[s]) << 10) + (cell_clamp(sy[s]) << 5)
                     + cell_clamp(sz[s]);
            uv[s] = (flat < SPLIT_FLAT) ? sm->tab[flat] : __ldg(&gtab[flat]);
        }

        #pragma unroll
        for (int s = 0; s < 6; s++) {
            unsigned u = uv[s];
            float dx = fmaf(-0.03125f,  (float)(u & 1023u),         sx[s]);
            float dy = fmaf(-0.015625f, (float)((u >> 10) & 2047u), sy[s]);
            float dz = fmaf(-0.015625f, (float)(u >> 21),           sz[s]);
            acc += sqrt_approx(dx*dx + dy*dy + dz*dz);
        }
    }

    // ---- block reduce + global accumulate + fused finalize ----
    #pragma unroll
    for (int o = 16; o; o >>= 1) acc += __shfl_xor_sync(0xffffffffu, acc, o);
    if ((tid & 31) == 0) sm->red[tid >> 5] = acc;
    __syncthreads();

    if (tid == 0) {
        float v = 0.f;
        #pragma unroll
        for (int i = 0; i < TPB/32; i++) v += sm->red[i];
        atomicAdd(&g_acc, (double)v);
        __threadfence();
        unsigned t = atomicAdd(&g_cnt, 1u);
        if (t == MAIN_GRID - 1) {
            __threadfence();
            double s = g_acc;
            out[0] = (float)(s / ((double)BATCH * (double)NPTS));
            g_acc = 0.0;
            g_cnt = 0u;
            __threadfence();
        }
    }
}

extern "C" void kernel_launch(void* const* d_in, const int* in_sizes, int n_in,
                              void* d_out, int out_size) {
    const float* prm     = (const float*)d_in[0];   // (64, 6, 4)
    const float* points  = (const float*)d_in[1];   // (64, 16384, 3)
    const float* closest = (const float*)d_in[2];   // (64, 32768, 3)
    float* out = (float*)d_out;

    cudaError_t e = cudaFuncSetAttribute(sdl_main_kernel,
                                         cudaFuncAttributeMaxDynamicSharedMemorySize,
                                         SMEM_BYTES);
    (void)e;   // on failure the launch below errors loudly (invalid config)

    sdl_repack_kernel<<<(BATCH * GCNT) / 256, 256>>>(closest);
    sdl_main_kernel<<<MAIN_GRID, TPB, SMEM_BYTES>>>(prm, points, out);
}